// round 12
// baseline (speedup 1.0000x reference)
#include <cuda_runtime.h>
#include <cuda_bf16.h>

#define RDIM 256
#define SDIM 256
#define NEG_INF (-1e30f)

// Dummy dynamic smem: sized 96KB at launch to cap residency at 2 CTAs/SM so
// that ~296 resident CTAs x 256KB tile = 76MB fits in the 126MB L2 and the
// row-pass re-read hits L2 instead of DRAM.
extern __shared__ char _resv[];

__device__ __forceinline__ void consider(
    float v, int s, float &a0, int &x0, float &a1, int &x1, float &a2, int &x2)
{
    if (v > a2) {                          // rare after warm-up (~17/256 taken)
        if (v > a0)      { a2 = a1; x2 = x1; a1 = a0; x1 = x0; a0 = v; x0 = s; }
        else if (v > a1) { a2 = a1; x2 = x1; a1 = v;  x1 = s; }
        else             { a2 = v;  x2 = s; }
    }
}

__global__ __launch_bounds__(512)
void ipm_kernel(const float* __restrict__ msm,
                const int* __restrict__ refm,     // bool promoted to int32
                const int* __restrict__ srcm,     // bool promoted to int32
                float* __restrict__ out_score,
                float* __restrict__ out_corr)     // bool output stored as float32
{
    const int p = blockIdx.x;
    const int tid = threadIdx.x;                  // 0..511

    const float* __restrict__ tile = msm + (size_t)p * RDIM * SDIM;
    float* __restrict__ oscore = out_score + (size_t)p * RDIM * SDIM;
    float* __restrict__ ocorr  = out_corr  + (size_t)p * RDIM * SDIM;

    // ---------------- zero-fill FIRST (independent stores drain under scans) --
    // __stcs: evict-first so the 268MB write stream doesn't evict tile lines
    // needed by the row-pass L2 re-read.
    {
        const float4 z4 = make_float4(0.f, 0.f, 0.f, 0.f);
        float4* zs = (float4*)oscore;
        float4* zc = (float4*)ocorr;
        #pragma unroll 8
        for (int i = tid; i < (RDIM * SDIM) / 4; i += 512) {
            __stcs(&zs[i], z4);
            __stcs(&zc[i], z4);
        }
    }

    // top-3 of RAW scores (exp is monotonic; exp applied to winners only)
    float b0 = NEG_INF, b1 = NEG_INF, b2 = NEG_INF;
    int   j0 = 0,       j1 = 0,       j2 = 0;

    if (tid < 256) {
        // ---- column top-3 for column t = tid (scan r; coalesced across lanes)
        const int t = tid;
        #pragma unroll 8
        for (int r = 0; r < RDIM; ++r) {
            float v = tile[r * SDIM + t];
            consider(v, r, b0, j0, b1, j1, b2, j2);
        }
    } else {
        // ---- row top-3 for row t = tid-256 (contiguous float4 per thread,
        //      L2-resident thanks to the 2-CTA/SM residency cap)
        const int t = tid - 256;
        const float4* __restrict__ row = (const float4*)(tile + (size_t)t * SDIM);
        #pragma unroll 8
        for (int j = 0; j < SDIM / 4; ++j) {
            float4 q = row[j];
            int s = 4 * j;
            consider(q.x, s + 0, b0, j0, b1, j1, b2, j2);
            consider(q.y, s + 1, b0, j0, b1, j1, b2, j2);
            consider(q.z, s + 2, b0, j0, b1, j1, b2, j2);
            consider(q.w, s + 3, b0, j0, b1, j1, b2, j2);
        }
    }

    __syncthreads();   // zero-fill by whole block visible before scatter

    // ---------------- scatter (exp applied to the 3 winners only) ------------
    float vs[3] = {__expf(b0), __expf(b1), __expf(b2)};
    int   is[3] = {j0, j1, j2};

    if (tid < 256) {
        // Column t's top-3 along R
        const int t = tid;
        const bool ms = srcm[(size_t)p * SDIM + t] != 0;
        #pragma unroll
        for (int k = 0; k < 3; ++k) {
            int r = is[k];
            float v = vs[k];
            atomicAdd(&oscore[r * SDIM + t], 0.5f * v);
            if (v > 0.0f && ms && refm[(size_t)p * RDIM + r] != 0)
                ocorr[r * SDIM + t] = 1.0f;   // idempotent write, benign race
        }
    } else {
        // Row t's top-3 along S
        const int t = tid - 256;
        const bool mr = refm[(size_t)p * RDIM + t] != 0;
        #pragma unroll
        for (int k = 0; k < 3; ++k) {
            int s = is[k];
            float v = vs[k];
            atomicAdd(&oscore[t * SDIM + s], 0.5f * v);
            if (v > 0.0f && mr && srcm[(size_t)p * SDIM + s] != 0)
                ocorr[t * SDIM + s] = 1.0f;
        }
    }
}

extern "C" void kernel_launch(void* const* d_in, const int* in_sizes, int n_in,
                              void* d_out, int out_size)
{
    // metadata order: matching_score_map [P,R,S] f32, node_corr_scores [P] f32 (unused),
    //                 ref_knn_masks [P,R] bool->int32, src_knn_masks [P,S] bool->int32
    const float* msm  = (const float*)d_in[0];
    const int*   refm = (const int*)d_in[2];
    const int*   srcm = (const int*)d_in[3];

    const int P = in_sizes[1];                 // node_corr_scores has P elements
    float* out_score = (float*)d_out;
    float* out_corr  = out_score + (size_t)P * RDIM * SDIM;  // bool output as float32

    // 96KB dummy dynamic smem -> 2 CTAs/SM residency cap (no allocation; this
    // is an attribute + launch-config change only). Idempotent per call.
    const int SMEM_CAP = 96 * 1024;
    cudaFuncSetAttribute(ipm_kernel, cudaFuncAttributeMaxDynamicSharedMemorySize, SMEM_CAP);

    ipm_kernel<<<P, 512, SMEM_CAP>>>(msm, refm, srcm, out_score, out_corr);
}

// round 13
// speedup vs baseline: 1.1335x; 1.1335x over previous
#include <cuda_runtime.h>
#include <cuda_bf16.h>

#define RDIM 256
#define SDIM 256
#define NEG_INF (-1e30f)

// Stable comparator: value descending, index ascending on ties (matches jax top_k).
__device__ __forceinline__ bool better(float a, int i, float b, int j)
{
    return (a > b) || (a == b && i < j);
}

// Merge two triples (each sorted by `better`) -> top-3 left in a-registers.
// Validated in R9 (rel_err 9e-8).
__device__ __forceinline__ void merge3(
    float &a0, int &i0, float &a1, int &i1, float &a2, int &i2,
    float b0, int j0, float b1, int j1, float b2, int j2)
{
    float o0, o1, o2; int p0, p1, p2;
    if (better(a0, i0, b0, j0)) { o0 = a0; p0 = i0; a0 = a1; i0 = i1; a1 = a2; i1 = i2; }
    else                        { o0 = b0; p0 = j0; b0 = b1; j0 = j1; b1 = b2; j1 = j2; }
    if (better(a0, i0, b0, j0)) { o1 = a0; p1 = i0; a0 = a1; i0 = i1; }
    else                        { o1 = b0; p1 = j0; b0 = b1; j0 = j1; }
    if (better(a0, i0, b0, j0)) { o2 = a0; p2 = i0; }
    else                        { o2 = b0; p2 = j0; }
    a0 = o0; i0 = p0; a1 = o1; i1 = p1; a2 = o2; i2 = p2;
}

// Sequential stable top-3 update (strict >, ascending index scan order).
__device__ __forceinline__ void consider(
    float v, int s, float &a0, int &x0, float &a1, int &x1, float &a2, int &x2)
{
    if (v > a2) {                          // rare after warm-up
        if (v > a0)      { a2 = a1; x2 = x1; a1 = a0; x1 = x0; a0 = v; x0 = s; }
        else if (v > a1) { a2 = a1; x2 = x1; a1 = v;  x1 = s; }
        else             { a2 = v;  x2 = s; }
    }
}

__global__ __launch_bounds__(1024)
void ipm_kernel(const float* __restrict__ msm,
                const int* __restrict__ refm,     // bool promoted to int32
                const int* __restrict__ srcm,     // bool promoted to int32
                float* __restrict__ out_score,
                float* __restrict__ out_corr)     // bool output stored as float32
{
    const int p = blockIdx.x;
    const int tid = threadIdx.x;                  // 0..1023

    const float* __restrict__ tile = msm + (size_t)p * RDIM * SDIM;
    float* __restrict__ oscore = out_score + (size_t)p * RDIM * SDIM;
    float* __restrict__ ocorr  = out_corr  + (size_t)p * RDIM * SDIM;

    __shared__ float s_v[1024][3];
    __shared__ int   s_i[1024][3];

    // ---------------- zero-fill FIRST (fire-and-forget, drains under scans) --
    {
        const float4 z4 = make_float4(0.f, 0.f, 0.f, 0.f);
        float4* zs = (float4*)oscore;
        float4* zc = (float4*)ocorr;
        #pragma unroll 16
        for (int i = tid; i < (RDIM * SDIM) / 4; i += 1024) {
            zs[i] = z4;
            zc[i] = z4;
        }
    }

    // ---------------- half-line scans: 128 elements per thread ---------------
    float b0 = NEG_INF, b1 = NEG_INF, b2 = NEG_INF;
    int   j0 = 0,       j1 = 0,       j2 = 0;

    if (tid < 512) {
        // column worker: column t, rows [h*128, h*128+128)
        const int t = tid & 255;
        const int h = tid >> 8;
        const int rbase = h * 128;
        #pragma unroll 8
        for (int i = 0; i < 128; ++i) {
            float v = tile[(rbase + i) * SDIM + t];
            consider(v, rbase + i, b0, j0, b1, j1, b2, j2);
        }
    } else {
        // row worker: row t, cols [h*128, h*128+128) as 32 contiguous float4
        const int u = tid - 512;
        const int t = u & 255;
        const int h = u >> 8;
        const float4* __restrict__ half = (const float4*)(tile + (size_t)t * SDIM + h * 128);
        const int sbase = h * 128;
        #pragma unroll 8
        for (int j = 0; j < 32; ++j) {
            float4 q = half[j];
            int s = sbase + 4 * j;
            consider(q.x, s + 0, b0, j0, b1, j1, b2, j2);
            consider(q.y, s + 1, b0, j0, b1, j1, b2, j2);
            consider(q.z, s + 2, b0, j0, b1, j1, b2, j2);
            consider(q.w, s + 3, b0, j0, b1, j1, b2, j2);
        }
    }

    // publish partial triples
    s_v[tid][0] = b0; s_v[tid][1] = b1; s_v[tid][2] = b2;
    s_i[tid][0] = j0; s_i[tid][1] = j1; s_i[tid][2] = j2;

    __syncthreads();   // zero-fill + all partials visible

    // ---------------- merge partner halves + scatter -------------------------
    if (tid < 256) {
        // column t = tid: merge (tid: rows 0-127) with (tid+256: rows 128-255)
        const int t = tid;
        float a0 = s_v[t][0],     a1 = s_v[t][1],     a2 = s_v[t][2];
        int   x0 = s_i[t][0],     x1 = s_i[t][1],     x2 = s_i[t][2];
        merge3(a0, x0, a1, x1, a2, x2,
               s_v[t + 256][0], s_i[t + 256][0],
               s_v[t + 256][1], s_i[t + 256][1],
               s_v[t + 256][2], s_i[t + 256][2]);

        const bool ms = srcm[(size_t)p * SDIM + t] != 0;
        float vs[3] = {__expf(a0), __expf(a1), __expf(a2)};
        int   is[3] = {x0, x1, x2};
        #pragma unroll
        for (int k = 0; k < 3; ++k) {
            int r = is[k];
            float v = vs[k];
            atomicAdd(&oscore[r * SDIM + t], 0.5f * v);
            if (v > 0.0f && ms && refm[(size_t)p * RDIM + r] != 0)
                ocorr[r * SDIM + t] = 1.0f;   // idempotent write, benign race
        }
    } else if (tid >= 512 && tid < 768) {
        // row t = tid-512: merge (tid: cols 0-127) with (tid+256: cols 128-255)
        const int t = tid - 512;
        float a0 = s_v[tid][0],   a1 = s_v[tid][1],   a2 = s_v[tid][2];
        int   x0 = s_i[tid][0],   x1 = s_i[tid][1],   x2 = s_i[tid][2];
        merge3(a0, x0, a1, x1, a2, x2,
               s_v[tid + 256][0], s_i[tid + 256][0],
               s_v[tid + 256][1], s_i[tid + 256][1],
               s_v[tid + 256][2], s_i[tid + 256][2]);

        const bool mr = refm[(size_t)p * RDIM + t] != 0;
        float vs[3] = {__expf(a0), __expf(a1), __expf(a2)};
        int   is[3] = {x0, x1, x2};
        #pragma unroll
        for (int k = 0; k < 3; ++k) {
            int s = is[k];
            float v = vs[k];
            atomicAdd(&oscore[t * SDIM + s], 0.5f * v);
            if (v > 0.0f && mr && srcm[(size_t)p * SDIM + s] != 0)
                ocorr[t * SDIM + s] = 1.0f;
        }
    }
}

extern "C" void kernel_launch(void* const* d_in, const int* in_sizes, int n_in,
                              void* d_out, int out_size)
{
    // metadata order: matching_score_map [P,R,S] f32, node_corr_scores [P] f32 (unused),
    //                 ref_knn_masks [P,R] bool->int32, src_knn_masks [P,S] bool->int32
    const float* msm  = (const float*)d_in[0];
    const int*   refm = (const int*)d_in[2];
    const int*   srcm = (const int*)d_in[3];

    const int P = in_sizes[1];                 // node_corr_scores has P elements
    float* out_score = (float*)d_out;
    float* out_corr  = out_score + (size_t)P * RDIM * SDIM;  // bool output as float32

    ipm_kernel<<<P, 1024>>>(msm, refm, srcm, out_score, out_corr);
}